// round 17
// baseline (speedup 1.0000x reference)
#include <cuda_runtime.h>
#include <cuda_fp16.h>
#include <math.h>
#include <stdint.h>

#define Bb 8
#define Ss 256
#define Tt 32
#define Dd 512

typedef unsigned long long ull;

// ---------------------------------------------------------------------------
// helpers (proven in R12-R16)
// ---------------------------------------------------------------------------
__device__ __forceinline__ uint32_t smem_to_u32(const void* p) {
    uint32_t a;
    asm("{ .reg .u64 t; cvta.to.shared.u64 t, %1; cvt.u32.u64 %0, t; }"
        : "=r"(a) : "l"(p));
    return a;
}
__device__ __forceinline__ void ldsm_x4(uint32_t* r, uint32_t addr) {
    asm volatile("ldmatrix.sync.aligned.m8n8.x4.shared.b16 {%0,%1,%2,%3}, [%4];"
        : "=r"(r[0]), "=r"(r[1]), "=r"(r[2]), "=r"(r[3]) : "r"(addr));
}
__device__ __forceinline__ void ldsm_x4_t(uint32_t* r, uint32_t addr) {
    asm volatile("ldmatrix.sync.aligned.m8n8.x4.trans.shared.b16 {%0,%1,%2,%3}, [%4];"
        : "=r"(r[0]), "=r"(r[1]), "=r"(r[2]), "=r"(r[3]) : "r"(addr));
}
__device__ __forceinline__ void mma_f16(float* d, const uint32_t* a, const uint32_t* b) {
    asm volatile("mma.sync.aligned.m16n8k16.row.col.f32.f16.f16.f32 "
        "{%0,%1,%2,%3}, {%4,%5,%6,%7}, {%8,%9}, {%0,%1,%2,%3};"
        : "+f"(d[0]), "+f"(d[1]), "+f"(d[2]), "+f"(d[3])
        : "r"(a[0]), "r"(a[1]), "r"(a[2]), "r"(a[3]), "r"(b[0]), "r"(b[1]));
}
__device__ __forceinline__ uint32_t pbh(__half a, __half b) {
    __half2 t; t.x = a; t.y = b;
    return *(uint32_t*)&t;
}
__device__ __forceinline__ ull pack2(float x, float y) {
    ull r;
    asm("mov.b64 %0, {%1, %2};" : "=l"(r) : "f"(x), "f"(y));
    return r;
}
__device__ __forceinline__ void unpack2(ull v, float& x, float& y) {
    asm("mov.b64 {%0, %1}, %2;" : "=f"(x), "=f"(y) : "l"(v));
}
__device__ __forceinline__ ull mul2(ull a, ull b) {
    ull d;
    asm("mul.rn.f32x2 %0, %1, %2;" : "=l"(d) : "l"(a), "l"(b));
    return d;
}
__device__ __forceinline__ ull fma2v(ull a, ull b, ull c) {
    ull d;
    asm("fma.rn.f32x2 %0, %1, %2, %3;" : "=l"(d) : "l"(a), "l"(b), "l"(c));
    return d;
}
__device__ __forceinline__ void cvt_sts(__half* dst, float4 v) {
    uint2 uh;
    uh.x = pbh(__float2half_rn(v.x), __float2half_rn(v.y));
    uh.y = pbh(__float2half_rn(v.z), __float2half_rn(v.w));
    *(uint2*)dst = uh;
}

// ---------------------------------------------------------------------------
// smem layout (float offsets). Total 50048 floats = 200192 bytes (< 227KB).
//   Hs  [256][36] f32  tanh H tile       0     .. 9216
//   Fs  [256][36] f32  tanh F tile       9216  .. 18432
//   Es  [256][32] f32  enc cols          18432 .. 26624
//   red2 [8][32][16] float2              26624 .. 34816
//   fin  [32][16] float2                 34816 .. 35840
//   encCh [256][72] half (staging)       35840 .. 45056   (also z chunks)
//   W1ch  [64][40] half                  45056 .. 46336   (also W3; Atile after GEMM)
//   W2ch  [64][40] half                  46336 .. 47616   (Ctile after GEMM)
//   W4ch  [64][40] half                  47616 .. 48896
//   outCh [32][72] half                  48896 .. 50048
// ---------------------------------------------------------------------------
#define HS_OFF   0
#define FS_OFF   9216
#define ES_OFF   18432
#define RED_OFF  26624
#define FIN_OFF  34816
#define STG_OFF  35840
#define W1_OFF   45056
#define W2_OFF   46336
#define W4_OFF   47616
#define OUT_OFF  48896
#define SM_FLOATS 50048
#define SM_BYTES (SM_FLOATS * 4)

// Write one warp's 16x16 fp32 fragment tile (two n8 MMAs) with bias+tanh.
// dst stride 36 floats.
__device__ __forceinline__ void frag_store(float* dst, int m, int n,
        const float* a0, const float* a1, const float* __restrict__ bias, int gn)
{
    float2 bl  = *(const float2*)&bias[gn];
    float2 bh2 = *(const float2*)&bias[gn + 8];
    float2 v;
    v.x = tanhf(a0[0] + bl.x);  v.y = tanhf(a0[1] + bl.y);
    *(float2*)&dst[m * 36 + n] = v;
    v.x = tanhf(a0[2] + bl.x);  v.y = tanhf(a0[3] + bl.y);
    *(float2*)&dst[(m + 8) * 36 + n] = v;
    v.x = tanhf(a1[0] + bh2.x); v.y = tanhf(a1[1] + bh2.y);
    *(float2*)&dst[m * 36 + n + 8] = v;
    v.x = tanhf(a1[2] + bh2.x); v.y = tanhf(a1[3] + bh2.y);
    *(float2*)&dst[(m + 8) * 36 + n + 8] = v;
}

// ---------------------------------------------------------------------------
// Fully fused kernel. Block = (d-tile 32, b), 1024 threads, 32 warps.
// Phase G: this block's own H/F/A/C output tiles via fp16 mma.sync
//   (H: M=256 N=32 K=512; F: K=128; A,C: M=32 via warps 0-7) into smem.
// Phase A: R15 attention (f32x2 + 8-way s-split) on the smem tiles.
// ---------------------------------------------------------------------------
__global__ void __launch_bounds__(1024)
fused_kernel(const float* __restrict__ outp, const float* __restrict__ enc,
             const float* __restrict__ z,
             const float* __restrict__ W1, const float* __restrict__ b1,
             const float* __restrict__ W2, const float* __restrict__ b2,
             const float* __restrict__ W3, const float* __restrict__ b3,
             const float* __restrict__ W4, const float* __restrict__ b4,
             float* __restrict__ concat, float* __restrict__ attn)
{
    extern __shared__ float sm[];
    float*  Hs    = sm + HS_OFF;
    float*  Fsm   = sm + FS_OFF;
    float*  Es    = sm + ES_OFF;
    float2* red2  = (float2*)(sm + RED_OFF);
    float2* fin   = (float2*)(sm + FIN_OFF);
    __half* encCh = (__half*)(sm + STG_OFF);
    __half* W1ch  = (__half*)(sm + W1_OFF);
    __half* W2ch  = (__half*)(sm + W2_OFF);
    __half* W4ch  = (__half*)(sm + W4_OFF);
    __half* outCh = (__half*)(sm + OUT_OFF);
    float*  Atile = sm + W1_OFF;   // aliases W1ch; written after final GEMM sync
    float*  Ctile = sm + W2_OFF;   // aliases W2ch

    const int tid  = threadIdx.x;
    const int lane = tid & 31;
    const int w    = tid >> 5;
    const int wm   = w & 15;       // H/F m-tile (16 rows)
    const int wn   = w >> 4;       // H/F n-tile (16 cols)
    const int d0   = blockIdx.x * 32;
    const int b    = blockIdx.y;
    const int n0   = d0;

    const uint32_t encB = smem_to_u32(encCh);
    const uint32_t w1B  = smem_to_u32(W1ch);
    const uint32_t w2B  = smem_to_u32(W2ch);
    const uint32_t w4B  = smem_to_u32(W4ch);
    const uint32_t outB = smem_to_u32(outCh);

    // Es: enc columns [d0, d0+32) for this batch (independent region)
    #pragma unroll
    for (int q = 0; q < 2; q++) {
        int idx = tid + q * 1024;
        int s = idx >> 3, dl = (idx & 7) << 2;
        *(float4*)&Es[s * 32 + dl] =
            *(const float4*)&enc[(size_t)(b * Ss + s) * Dd + d0 + dl];
    }

    // ---------------- Phase F: Fs = tanh(z_b @ W3[:,n0..] + b3) ----------------
    float fa0[4] = {0,0,0,0}, fa1[4] = {0,0,0,0};
    for (int c = 0; c < 2; c++) {
        const int k0 = c * 64;
        __syncthreads();
        #pragma unroll
        for (int q = 0; q < 5; q++) {
            int i = tid + q * 1024;
            if (i < 4096) {
                int r = i >> 4, cg = (i & 15) * 4;
                cvt_sts(&encCh[r * 72 + cg],
                        *(const float4*)&z[(size_t)(b * Ss + r) * 128 + k0 + cg]);
            } else if (i < 4608) {
                int j = i - 4096; int r = j >> 3, cg = (j & 7) * 4;
                cvt_sts(&W1ch[r * 40 + cg],
                        *(const float4*)&W3[(size_t)(k0 + r) * Dd + n0 + cg]);
            }
        }
        __syncthreads();
        #pragma unroll
        for (int ks = 0; ks < 4; ks++) {
            const int kk = ks * 16;
            uint32_t ah[4], bh[4];
            int row = wm * 16 + (lane & 15);
            ldsm_x4(ah, encB + (uint32_t)(row * 72 + kk + (lane >> 4) * 8) * 2);
            int kr = kk + (lane & 15), nc = wn * 16 + (lane >> 4) * 8;
            ldsm_x4_t(bh, w1B + (uint32_t)(kr * 40 + nc) * 2);
            mma_f16(fa0, ah, bh);
            mma_f16(fa1, ah, bh + 2);
        }
    }
    {
        int m = wm * 16 + (lane >> 2);
        int n = wn * 16 + (lane & 3) * 2;
        frag_store(Fsm, m, n, fa0, fa1, b3, n0 + n);
    }

    // ------------- Phase H (+A/C): K=512, 8 chunks of 64 -------------
    float ha0[4] = {0,0,0,0}, ha1[4] = {0,0,0,0};
    float xa0[4] = {0,0,0,0}, xa1[4] = {0,0,0,0};
    const int sel = w >> 2;                 // warps 0-3: A (W2/b2), 4-7: C (W4/b4)
    const int wmx = w & 1, wnx = (w >> 1) & 1;
    for (int c = 0; c < 8; c++) {
        const int k0 = c * 64;
        __syncthreads();
        #pragma unroll
        for (int q = 0; q < 6; q++) {
            int i = tid + q * 1024;
            if (i < 4096) {
                int r = i >> 4, cg = (i & 15) * 4;
                cvt_sts(&encCh[r * 72 + cg],
                        *(const float4*)&enc[(size_t)(b * Ss + r) * Dd + k0 + cg]);
            } else if (i < 4608) {
                int j = i - 4096; int r = j >> 3, cg = (j & 7) * 4;
                cvt_sts(&W1ch[r * 40 + cg],
                        *(const float4*)&W1[(size_t)(k0 + r) * Dd + n0 + cg]);
            } else if (i < 5120) {
                int j = i - 4608; int r = j >> 3, cg = (j & 7) * 4;
                cvt_sts(&W2ch[r * 40 + cg],
                        *(const float4*)&W2[(size_t)(k0 + r) * Dd + n0 + cg]);
            } else if (i < 5632) {
                int j = i - 5120; int r = j >> 3, cg = (j & 7) * 4;
                cvt_sts(&W4ch[r * 40 + cg],
                        *(const float4*)&W4[(size_t)(k0 + r) * Dd + n0 + cg]);
            } else {
                int j = i - 5632; int r = j >> 4, cg = (j & 15) * 4;
                cvt_sts(&outCh[r * 72 + cg],
                        *(const float4*)&outp[(size_t)(b * Tt + r) * Dd + k0 + cg]);
            }
        }
        __syncthreads();
        #pragma unroll
        for (int ks = 0; ks < 4; ks++) {
            const int kk = ks * 16;
            uint32_t ah[4], bh[4];
            int row = wm * 16 + (lane & 15);
            ldsm_x4(ah, encB + (uint32_t)(row * 72 + kk + (lane >> 4) * 8) * 2);
            int kr = kk + (lane & 15), nc = wn * 16 + (lane >> 4) * 8;
            ldsm_x4_t(bh, w1B + (uint32_t)(kr * 40 + nc) * 2);
            mma_f16(ha0, ah, bh);
            mma_f16(ha1, ah, bh + 2);
        }
        if (w < 8) {
            #pragma unroll
            for (int ks = 0; ks < 4; ks++) {
                const int kk = ks * 16;
                uint32_t ah[4], bh[4];
                int row = wmx * 16 + (lane & 15);
                ldsm_x4(ah, outB + (uint32_t)(row * 72 + kk + (lane >> 4) * 8) * 2);
                int kr = kk + (lane & 15), nc = wnx * 16 + (lane >> 4) * 8;
                ldsm_x4_t(bh, (sel ? w4B : w2B) + (uint32_t)(kr * 40 + nc) * 2);
                mma_f16(xa0, ah, bh);
                mma_f16(xa1, ah, bh + 2);
            }
        }
    }
    __syncthreads();    // all W1ch/W2ch MMA reads done before Atile/Ctile overwrite
    {
        int m = wm * 16 + (lane >> 2);
        int n = wn * 16 + (lane & 3) * 2;
        frag_store(Hs, m, n, ha0, ha1, b1, n0 + n);
    }
    if (w < 8) {
        int m = wmx * 16 + (lane >> 2);
        int n = wnx * 16 + (lane & 3) * 2;
        frag_store(sel ? Ctile : Atile, m, n, xa0, xa1, sel ? b4 : b2, n0 + n);
    }
    __syncthreads();

    // ---------------- Phase attn (R15 proven structure) ----------------
    const float L2E = 1.4426950408889634f;
    const int dp  = tid & 15;
    const int tq  = (tid >> 4) & 7;
    const int sq  = tid >> 7;            // 0..7
    const int dl2 = dp * 2;

    ull a2[4], c2[4];
    #pragma unroll
    for (int ti = 0; ti < 4; ti++) {
        int t = tq * 4 + ti;
        float2 av = *(const float2*)&Atile[t * 36 + dl2];
        float2 cv = *(const float2*)&Ctile[t * 36 + dl2];
        a2[ti] = pack2(av.x * L2E, av.y * L2E);
        c2[ti] = pack2(cv.x * L2E, cv.y * L2E);
    }

    const int s0 = sq * 32;

    float2 ps[4];
    #pragma unroll
    for (int ti = 0; ti < 4; ti++) ps[ti] = make_float2(0.f, 0.f);
    #pragma unroll 4
    for (int s = s0; s < s0 + 32; s++) {
        float2 hf = *(const float2*)&Hs[s * 36 + dl2];
        float2 ff = *(const float2*)&Fsm[s * 36 + dl2];
        ull h2 = pack2(hf.x, hf.y);
        ull f2 = pack2(ff.x, ff.y);
        #pragma unroll
        for (int ti = 0; ti < 4; ti++) {
            ull l2 = fma2v(a2[ti], h2, mul2(c2[ti], f2));
            float lx, ly; unpack2(l2, lx, ly);
            ps[ti].x += exp2f(lx);
            ps[ti].y += exp2f(ly);
        }
    }
    #pragma unroll
    for (int ti = 0; ti < 4; ti++)
        red2[sq * 512 + (tq * 4 + ti) * 16 + dp] = ps[ti];
    __syncthreads();
    if (tid < 512) {
        float2 sacc = red2[tid];
        #pragma unroll
        for (int k = 1; k < 8; k++) {
            float2 r = red2[k * 512 + tid];
            sacc.x += r.x; sacc.y += r.y;
        }
        fin[tid] = make_float2(1.f / sacc.x, 1.f / sacc.y);
    }
    __syncthreads();
    ull inv2[4];
    #pragma unroll
    for (int ti = 0; ti < 4; ti++) {
        float2 iv = fin[(tq * 4 + ti) * 16 + dp];
        inv2[ti] = pack2(iv.x, iv.y);
    }

    float2 pc[4];
    #pragma unroll
    for (int ti = 0; ti < 4; ti++) pc[ti] = make_float2(0.f, 0.f);
    #pragma unroll 2
    for (int s = s0; s < s0 + 32; s++) {
        float2 hf = *(const float2*)&Hs[s * 36 + dl2];
        float2 ff = *(const float2*)&Fsm[s * 36 + dl2];
        float2 ef = *(const float2*)&Es[s * 32 + dl2];
        ull h2 = pack2(hf.x, hf.y);
        ull f2 = pack2(ff.x, ff.y);
        #pragma unroll
        for (int ti = 0; ti < 4; ti++) {
            ull l2 = fma2v(a2[ti], h2, mul2(c2[ti], f2));
            float lx, ly; unpack2(l2, lx, ly);
            ull g2 = mul2(pack2(exp2f(lx), exp2f(ly)), inv2[ti]);
            float gx, gy; unpack2(g2, gx, gy);
            int m = b * Tt + tq * 4 + ti;
            *(float2*)&attn[((size_t)m * Ss + s) * Dd + d0 + dl2] = make_float2(gx, gy);
            pc[ti].x = fmaf(gx, ef.x, pc[ti].x);
            pc[ti].y = fmaf(gy, ef.y, pc[ti].y);
        }
    }
    #pragma unroll
    for (int ti = 0; ti < 4; ti++)
        red2[sq * 512 + (tq * 4 + ti) * 16 + dp] = pc[ti];
    __syncthreads();
    if (tid < 512) {
        float2 cacc = red2[tid];
        #pragma unroll
        for (int k = 1; k < 8; k++) {
            float2 r = red2[k * 512 + tid];
            cacc.x += r.x; cacc.y += r.y;
        }
        int t  = tid >> 4;
        int dq = tid & 15;
        int m  = b * Tt + t;
        *(float2*)&concat[(size_t)m * (2 * Dd) + Dd + d0 + dq * 2] = cacc;
    } else {
        int idx = tid - 512;
        int t  = idx >> 4;
        int dq = idx & 15;
        int m  = b * Tt + t;
        *(float2*)&concat[(size_t)m * (2 * Dd) + d0 + dq * 2] =
            *(const float2*)&outp[(size_t)m * Dd + d0 + dq * 2];
    }
}

// ---------------------------------------------------------------------------
extern "C" void kernel_launch(void* const* d_in, const int* in_sizes, int n_in,
                              void* d_out, int out_size)
{
    const float* output = (const float*)d_in[0];   // [8,32,512]
    const float* enc    = (const float*)d_in[1];   // [256,8,512] flat [2048,512]
    const float* z      = (const float*)d_in[2];   // [8,256,128] flat [2048,128]
    const float* W1 = (const float*)d_in[3];
    const float* b1 = (const float*)d_in[4];
    const float* W2 = (const float*)d_in[5];
    const float* b2 = (const float*)d_in[6];
    const float* W3 = (const float*)d_in[7];
    const float* b3 = (const float*)d_in[8];
    const float* W4 = (const float*)d_in[9];
    const float* b4 = (const float*)d_in[10];

    float* concat = (float*)d_out;                       // [8,32,1024]
    float* attn   = concat + (size_t)Bb * Tt * 2 * Dd;   // [8,32,256,512]

    cudaFuncSetAttribute(fused_kernel, cudaFuncAttributeMaxDynamicSharedMemorySize, SM_BYTES);
    fused_kernel<<<dim3(16, Bb), 1024, SM_BYTES>>>(output, enc, z,
                                                   W1, b1, W2, b2, W3, b3, W4, b4,
                                                   concat, attn);
}